// round 1
// baseline (speedup 1.0000x reference)
#include <cuda_runtime.h>
#include <cstdint>

#define BATCH 8
#define T_FULL 2048
#define C_DIM 1024
#define H_DIM 64
#define TA 1024
#define TB 1024
#define R_MERGE 512
#define RB (R_MERGE*BATCH)   /* 4096 */
#define NROWS (BATCH*TA)     /* 8192 */
#define X_ELEMS (BATCH*T_FULL*C_DIM)  /* 16777216 */

// ---------------- scratch (__device__ globals; no allocation) ----------------
__device__ unsigned long long g_bdup[BATCH*TB*H_DIM];   // normalized b, duplicated (v,v) as f32x2
__device__ unsigned long long g_pack[NROWS];            // per a-row: (flip(max)<<32)|(1023-argmax)
__device__ int    g_flags[NROWS];                       // 1 = merged
__device__ int    g_table[BATCH*T_FULL];                // output row -> token code (2i even / 2j+1 odd / -1 tail)
__device__ float4 g_acc[BATCH*TB*C_DIM/4];              // scatter accumulator (32MB)
__device__ float  g_sizeacc[BATCH*TB];                  // scatter size accumulator

// monotone float -> u32 map (order preserving for all floats)
__device__ __forceinline__ unsigned fflip(float f) {
    unsigned u = __float_as_uint(f);
    return (u & 0x80000000u) ? ~u : (u | 0x80000000u);
}

// ---------------- init: zero accumulators ----------------
__global__ void k_init() {
    size_t n4 = (size_t)BATCH*TB*C_DIM/4;
    size_t stride = (size_t)gridDim.x*blockDim.x;
    float4 z = make_float4(0.f,0.f,0.f,0.f);
    for (size_t i = (size_t)blockIdx.x*blockDim.x + threadIdx.x; i < n4; i += stride)
        g_acc[i] = z;
    int t = blockIdx.x*blockDim.x + threadIdx.x;
    if (t < NROWS) { g_pack[t] = 0ULL; g_sizeacc[t] = 0.f; }
}

// ---------------- normalize odd tokens (b side), store duplicated f32x2 ----------------
__global__ void k_norm_b(const float* __restrict__ metric) {
    int warp = (blockIdx.x*blockDim.x + threadIdx.x) >> 5;
    int lane = threadIdx.x & 31;
    if (warp >= BATCH*TB) return;
    int b = warp / TB, j = warp % TB;
    const float* row = metric + ((size_t)(b*T_FULL + 2*j + 1))*H_DIM;
    float v0 = row[lane], v1 = row[lane + 32];
    float ss = v0*v0 + v1*v1;
    #pragma unroll
    for (int o = 16; o; o >>= 1) ss += __shfl_xor_sync(0xffffffffu, ss, o);
    float inv = 1.0f / sqrtf(ss);
    float n0 = v0*inv, n1 = v1*inv;
    unsigned long long p0, p1;
    asm("mov.b64 %0, {%1,%1};" : "=l"(p0) : "r"(__float_as_uint(n0)));
    asm("mov.b64 %0, {%1,%1};" : "=l"(p1) : "r"(__float_as_uint(n1)));
    g_bdup[(size_t)warp*H_DIM + lane]      = p0;
    g_bdup[(size_t)warp*H_DIM + lane + 32] = p1;
}

// ---------------- scores: per a-row max/argmax over all b via FFMA2 ----------------
#define JC 64
__global__ void __launch_bounds__(128) k_scores(const float* __restrict__ metric) {
    __shared__ unsigned long long bsh[JC*H_DIM];   // 32 KB
    int jchunk = blockIdx.x;      // 0..15
    int atile  = blockIdx.y;      // 0..3
    int b      = blockIdx.z;      // 0..7
    int tid = threadIdx.x;

    const unsigned long long* bsrc = g_bdup + ((size_t)(b*TB + jchunk*JC))*H_DIM;
    for (int i = tid; i < JC*H_DIM; i += 128) bsh[i] = bsrc[i];

    // two a-rows per thread, normalized on the fly, packed as f32x2 (row0 lo, row1 hi)
    int r0 = atile*256 + tid;
    int r1 = r0 + 128;
    const float* a0 = metric + ((size_t)(b*T_FULL + 2*r0))*H_DIM;
    const float* a1 = metric + ((size_t)(b*T_FULL + 2*r1))*H_DIM;
    float va0[H_DIM], va1[H_DIM];
    float ss0 = 0.f, ss1 = 0.f;
    #pragma unroll
    for (int k = 0; k < H_DIM; k++) {
        va0[k] = a0[k]; ss0 += va0[k]*va0[k];
        va1[k] = a1[k]; ss1 += va1[k]*va1[k];
    }
    float i0 = 1.0f / sqrtf(ss0), i1 = 1.0f / sqrtf(ss1);
    unsigned long long ap[H_DIM];
    #pragma unroll
    for (int k = 0; k < H_DIM; k++) {
        float f0 = va0[k]*i0, f1 = va1[k]*i1;
        asm("mov.b64 %0, {%1,%2};" : "=l"(ap[k]) : "f"(f0), "f"(f1));
    }
    __syncthreads();

    float m0 = -2.f, m1 = -2.f;
    int j0 = 0, j1 = 0;
    for (int j = 0; j < JC; j++) {
        const unsigned long long* bj = &bsh[j*H_DIM];
        unsigned long long ac0 = 0ULL, ac1 = 0ULL, ac2 = 0ULL, ac3 = 0ULL;
        #pragma unroll
        for (int k = 0; k < H_DIM; k += 4) {
            asm("fma.rn.f32x2 %0, %1, %2, %0;" : "+l"(ac0) : "l"(ap[k+0]), "l"(bj[k+0]));
            asm("fma.rn.f32x2 %0, %1, %2, %0;" : "+l"(ac1) : "l"(ap[k+1]), "l"(bj[k+1]));
            asm("fma.rn.f32x2 %0, %1, %2, %0;" : "+l"(ac2) : "l"(ap[k+2]), "l"(bj[k+2]));
            asm("fma.rn.f32x2 %0, %1, %2, %0;" : "+l"(ac3) : "l"(ap[k+3]), "l"(bj[k+3]));
        }
        asm("add.rn.f32x2 %0, %0, %1;" : "+l"(ac0) : "l"(ac1));
        asm("add.rn.f32x2 %0, %0, %1;" : "+l"(ac2) : "l"(ac3));
        asm("add.rn.f32x2 %0, %0, %1;" : "+l"(ac0) : "l"(ac2));
        float d0 = __uint_as_float((unsigned)(ac0 & 0xffffffffu));
        float d1 = __uint_as_float((unsigned)(ac0 >> 32));
        int jg = jchunk*JC + j;
        if (d0 > m0) { m0 = d0; j0 = jg; }   // strict > keeps first max (matches argmax)
        if (d1 > m1) { m1 = d1; j1 = jg; }
    }
    unsigned long long p0 = ((unsigned long long)fflip(m0) << 32) | (unsigned)(1023 - j0);
    unsigned long long p1 = ((unsigned long long)fflip(m1) << 32) | (unsigned)(1023 - j1);
    atomicMax(&g_pack[b*TA + r0], p0);
    atomicMax(&g_pack[b*TA + r1], p1);
}

// ---------------- exact top-RB selection via 4-pass radix select ----------------
__global__ void k_topk() {
    extern __shared__ unsigned su[];     // NROWS u32 (32KB)
    __shared__ unsigned shist[256];
    __shared__ unsigned s_prefix, s_kneed;
    int tid = threadIdx.x;
    for (int i = tid; i < NROWS; i += 1024) su[i] = (unsigned)(g_pack[i] >> 32);
    if (tid == 0) { s_prefix = 0u; s_kneed = RB; }
    __syncthreads();

    for (int byte = 3; byte >= 0; byte--) {
        int shift = byte*8;
        unsigned maskhi = (byte == 3) ? 0u : (0xFFFFFFFFu << ((byte+1)*8));
        if (tid < 256) shist[tid] = 0u;
        __syncthreads();
        unsigned pref = s_prefix, kneed = s_kneed;
        for (int i = tid; i < NROWS; i += 1024) {
            unsigned u = su[i];
            if ((u & maskhi) == pref) atomicAdd(&shist[(u >> shift) & 255u], 1u);
        }
        __syncthreads();
        if (tid == 0) {
            unsigned cum = 0; int bin = 255;
            for (; bin > 0; bin--) {
                if (cum + shist[bin] >= kneed) break;
                cum += shist[bin];
            }
            s_prefix = pref | ((unsigned)bin << shift);
            s_kneed  = kneed - cum;
        }
        __syncthreads();
    }
    unsigned thr = s_prefix;
    int kprime = (int)s_kneed;    // how many == thr to take (smallest indices first)
    for (int i = tid; i < NROWS; i += 1024) {
        unsigned u = su[i];
        int f = 0;
        if (u > thr) f = 1;
        else if (u == thr) {
            int r = 0;
            for (int m = 0; m < i; m++) r += (su[m] == thr);
            f = (r < kprime);
        }
        g_flags[i] = f;
    }
}

// ---------------- per-batch output-order table ----------------
__global__ void k_plan() {
    __shared__ int s[1024];
    int b = blockIdx.x, tid = threadIdx.x;
    int f = g_flags[b*TA + tid];
    s[tid] = f;
    __syncthreads();
    #pragma unroll
    for (int o = 1; o < 1024; o <<= 1) {
        int v = (tid >= o) ? s[tid - o] : 0;
        __syncthreads();
        s[tid] += v;
        __syncthreads();
    }
    int mb = s[1023];           // merged count in this batch
    int rank_m = s[tid] - f;    // exclusive merged rank
    int* tab = g_table + b*T_FULL;
    if (f) tab[2048 - mb + rank_m] = -1;          // merged src -> tail slot
    else   tab[tid - rank_m]       = 2*tid;       // unmerged src, original order
    tab[(1024 - mb) + tid] = 2*tid + 1;           // dst rows
}

// ---------------- scatter merged src rows into accumulator ----------------
__global__ void k_scatter(const float* __restrict__ x, const float* __restrict__ size) {
    int i = blockIdx.x;
    if (!g_flags[i]) return;
    int b = i >> 10, il = i & 1023;
    int j = 1023 - (int)(g_pack[i] & 0xffffffffu);
    float sv = size[b*T_FULL + 2*il];
    const float* xrow = x + ((size_t)(b*T_FULL + 2*il))*C_DIM;
    float* accrow = reinterpret_cast<float*>(g_acc) + ((size_t)(b*TB + j))*C_DIM;
    for (int c = threadIdx.x; c < C_DIM; c += 128)
        atomicAdd(&accrow[c], xrow[c]*sv);
    if (threadIdx.x == 0) atomicAdd(&g_sizeacc[b*TB + j], sv);
}

// ---------------- final gather/divide + size_s + pad_s ----------------
__global__ void __launch_bounds__(256) k_out(const float* __restrict__ x,
                                             const float* __restrict__ size,
                                             float* __restrict__ out) {
    int row = blockIdx.x;               // b*2048 + t
    int b = row >> 11;
    int tid = threadIdx.x;
    int code = g_table[row];
    float4* orow = reinterpret_cast<float4*>(out + (size_t)row*C_DIM);

    if (code < 0) {                     // merged tail slot: zeros, size 0, pad 1
        orow[tid] = make_float4(0.f,0.f,0.f,0.f);
        if (tid == 0) { out[X_ELEMS + row] = 0.f; out[X_ELEMS + BATCH*T_FULL + row] = 1.f; }
        return;
    }
    int tok = code;
    const float4* xrow = reinterpret_cast<const float4*>(x + ((size_t)(b*T_FULL + tok))*C_DIM);
    float sv = size[b*T_FULL + tok];
    float4 v = xrow[tid];
    float ssum, invd;
    float4 r;
    if (code & 1) {                     // dst row: add accumulated merges
        int j = code >> 1;
        float sadd = g_sizeacc[b*TB + j];
        ssum = sv + sadd;
        invd = 1.0f / (ssum + 1e-4f);
        if (sadd != 0.f) {
            const float4* arow = reinterpret_cast<const float4*>(
                reinterpret_cast<const float*>(g_acc) + ((size_t)(b*TB + j))*C_DIM);
            float4 a = arow[tid];
            r.x = (v.x*sv + a.x)*invd; r.y = (v.y*sv + a.y)*invd;
            r.z = (v.z*sv + a.z)*invd; r.w = (v.w*sv + a.w)*invd;
        } else {
            r.x = v.x*sv*invd; r.y = v.y*sv*invd; r.z = v.z*sv*invd; r.w = v.w*sv*invd;
        }
    } else {                            // unmerged src row
        ssum = sv;
        invd = 1.0f / (sv + 1e-4f);
        r.x = v.x*sv*invd; r.y = v.y*sv*invd; r.z = v.z*sv*invd; r.w = v.w*sv*invd;
    }
    orow[tid] = r;
    if (tid == 0) { out[X_ELEMS + row] = ssum; out[X_ELEMS + BATCH*T_FULL + row] = 0.f; }
}

// ---------------- launch ----------------
extern "C" void kernel_launch(void* const* d_in, const int* in_sizes, int n_in,
                              void* d_out, int out_size) {
    const float* x      = (const float*)d_in[0];
    const float* metric = (const float*)d_in[1];
    const float* size   = (const float*)d_in[2];
    float* out = (float*)d_out;
    (void)in_sizes; (void)n_in; (void)out_size;

    k_init<<<2048, 256>>>();
    k_norm_b<<<1024, 256>>>(metric);
    dim3 g2(TB/JC, 4, BATCH);          // (16, 4, 8)
    k_scores<<<g2, 128>>>(metric);
    k_topk<<<1, 1024, NROWS*sizeof(unsigned)>>>();
    k_plan<<<BATCH, 1024>>>();
    k_scatter<<<NROWS, 128>>>(x, size);
    k_out<<<BATCH*T_FULL, 256>>>(x, size, out);
}

// round 2
// speedup vs baseline: 1.2189x; 1.2189x over previous
#include <cuda_runtime.h>
#include <cstdint>

#define BATCH 8
#define T_FULL 2048
#define C_DIM 1024
#define H_DIM 64
#define TA 1024
#define TB 1024
#define R_MERGE 512
#define RB (R_MERGE*BATCH)   /* 4096 */
#define NROWS (BATCH*TA)     /* 8192 */
#define X_ELEMS (BATCH*T_FULL*C_DIM)  /* 16777216 */

// ---------------- scratch (__device__ globals; zero-initialized .bss) ----------------
__device__ unsigned long long g_pack[NROWS];     // per a-row: (flip(max)<<32)|(1023-argmax); reset by k_topk
__device__ int g_flags[NROWS];                   // 1 = merged
__device__ int g_table[BATCH*T_FULL];            // output row -> token code (2i even / 2j+1 odd / -1 tail)
__device__ int g_dstoff[NROWS];                  // per dst (b*TB+j): start offset into g_dstlist
__device__ int g_dstdeg[NROWS];                  // per dst: number of merged srcs
__device__ int g_dstlist[RB];                    // merged src a-row indices grouped by dst

// monotone float -> u32 map (order preserving)
__device__ __forceinline__ unsigned fflip(float f) {
    unsigned u = __float_as_uint(f);
    return (u & 0x80000000u) ? ~u : (u | 0x80000000u);
}

// ---------------- scores: per a-row max/argmax over all b via FFMA2 ----------------
#define JC 64
__global__ void __launch_bounds__(128, 2) k_scores(const float* __restrict__ metric) {
    __shared__ unsigned long long bsh[JC*H_DIM];   // 32 KB, (v,v) duplicated f32x2
    int jchunk = blockIdx.x;      // 0..15
    int atile  = blockIdx.y;      // 0..3
    int b      = blockIdx.z;      // 0..7
    int tid = threadIdx.x, lane = tid & 31, warp = tid >> 5;

    // load + normalize b rows (odd tokens) into smem, duplicated as f32x2
    for (int jj = warp; jj < JC; jj += 4) {
        const float* row = metric + ((size_t)(b*T_FULL + 2*(jchunk*JC + jj) + 1))*H_DIM;
        float v0 = row[lane], v1 = row[lane + 32];
        float ss = v0*v0 + v1*v1;
        #pragma unroll
        for (int o = 16; o; o >>= 1) ss += __shfl_xor_sync(0xffffffffu, ss, o);
        float inv = 1.0f / sqrtf(ss);
        float n0 = v0*inv, n1 = v1*inv;
        unsigned long long p0, p1;
        asm("mov.b64 %0, {%1,%1};" : "=l"(p0) : "r"(__float_as_uint(n0)));
        asm("mov.b64 %0, {%1,%1};" : "=l"(p1) : "r"(__float_as_uint(n1)));
        bsh[jj*H_DIM + lane]      = p0;
        bsh[jj*H_DIM + lane + 32] = p1;
    }

    // two a-rows per thread, RAW values packed (row0 lo, row1 hi); scale dot at the end
    int r0 = atile*256 + tid;
    int r1 = r0 + 128;
    const float4* a0 = (const float4*)(metric + ((size_t)(b*T_FULL + 2*r0))*H_DIM);
    const float4* a1 = (const float4*)(metric + ((size_t)(b*T_FULL + 2*r1))*H_DIM);
    unsigned long long ap[H_DIM];
    float ss0 = 0.f, ss1 = 0.f;
    #pragma unroll
    for (int k = 0; k < H_DIM/4; k++) {
        float4 f0 = a0[k], f1 = a1[k];
        ss0 += f0.x*f0.x + f0.y*f0.y + f0.z*f0.z + f0.w*f0.w;
        ss1 += f1.x*f1.x + f1.y*f1.y + f1.z*f1.z + f1.w*f1.w;
        asm("mov.b64 %0, {%1,%2};" : "=l"(ap[4*k+0]) : "f"(f0.x), "f"(f1.x));
        asm("mov.b64 %0, {%1,%2};" : "=l"(ap[4*k+1]) : "f"(f0.y), "f"(f1.y));
        asm("mov.b64 %0, {%1,%2};" : "=l"(ap[4*k+2]) : "f"(f0.z), "f"(f1.z));
        asm("mov.b64 %0, {%1,%2};" : "=l"(ap[4*k+3]) : "f"(f0.w), "f"(f1.w));
    }
    float i0 = 1.0f / sqrtf(ss0), i1 = 1.0f / sqrtf(ss1);
    __syncthreads();

    float m0 = -3e38f, m1 = -3e38f;
    int j0 = 0, j1 = 0;
    for (int j = 0; j < JC; j++) {
        const ulonglong2* bj = (const ulonglong2*)&bsh[j*H_DIM];
        unsigned long long ac0 = 0ULL, ac1 = 0ULL, ac2 = 0ULL, ac3 = 0ULL;
        #pragma unroll
        for (int k2 = 0; k2 < H_DIM/2; k2 += 2) {
            ulonglong2 q0 = bj[k2], q1 = bj[k2+1];
            asm("fma.rn.f32x2 %0, %1, %2, %0;" : "+l"(ac0) : "l"(ap[2*k2+0]), "l"(q0.x));
            asm("fma.rn.f32x2 %0, %1, %2, %0;" : "+l"(ac1) : "l"(ap[2*k2+1]), "l"(q0.y));
            asm("fma.rn.f32x2 %0, %1, %2, %0;" : "+l"(ac2) : "l"(ap[2*k2+2]), "l"(q1.x));
            asm("fma.rn.f32x2 %0, %1, %2, %0;" : "+l"(ac3) : "l"(ap[2*k2+3]), "l"(q1.y));
        }
        asm("add.rn.f32x2 %0, %0, %1;" : "+l"(ac0) : "l"(ac1));
        asm("add.rn.f32x2 %0, %0, %1;" : "+l"(ac2) : "l"(ac3));
        asm("add.rn.f32x2 %0, %0, %1;" : "+l"(ac0) : "l"(ac2));
        float d0 = __uint_as_float((unsigned)(ac0 & 0xffffffffu)) * i0;
        float d1 = __uint_as_float((unsigned)(ac0 >> 32)) * i1;
        int jg = jchunk*JC + j;
        if (d0 > m0) { m0 = d0; j0 = jg; }   // strict > keeps first max
        if (d1 > m1) { m1 = d1; j1 = jg; }
    }
    unsigned long long p0 = ((unsigned long long)fflip(m0) << 32) | (unsigned)(1023 - j0);
    unsigned long long p1 = ((unsigned long long)fflip(m1) << 32) | (unsigned)(1023 - j1);
    atomicMax(&g_pack[b*TA + r0], p0);
    atomicMax(&g_pack[b*TA + r1], p1);
}

// ---------------- top-RB selection + flags + merge-list build (one CTA) ----------------
__global__ void __launch_bounds__(1024) k_topk() {
    __shared__ unsigned sarr[NROWS];     // 32KB: reused as counts, then cursor
    __shared__ unsigned shist[256];
    __shared__ unsigned sscan[1024];
    __shared__ unsigned s_prefix, s_kneed;
    int tid = threadIdx.x;
    int base = tid * 8;

    // load owned 8 rows into registers; reset g_pack for next graph replay
    unsigned uv[8]; int dlow[8];
    #pragma unroll
    for (int q = 0; q < 8; q++) {
        unsigned long long p = g_pack[base + q];
        uv[q]   = (unsigned)(p >> 32);
        dlow[q] = (int)(p & 0xffffffffu);
        g_pack[base + q] = 0ULL;
    }
    if (tid == 0) { s_prefix = 0u; s_kneed = RB; }
    __syncthreads();

    // 4-pass radix select (exact threshold)
    for (int byte = 3; byte >= 0; byte--) {
        int shift = byte * 8;
        unsigned maskhi = (byte == 3) ? 0u : (0xFFFFFFFFu << ((byte + 1) * 8));
        if (tid < 256) shist[tid] = 0u;
        __syncthreads();
        unsigned pref = s_prefix, kneed = s_kneed;
        #pragma unroll
        for (int q = 0; q < 8; q++) {
            unsigned u = uv[q];
            if ((u & maskhi) == pref) atomicAdd(&shist[(u >> shift) & 255u], 1u);
        }
        __syncthreads();
        // inclusive suffix sums over shist
        for (int o = 1; o < 256; o <<= 1) {
            unsigned add = 0;
            if (tid < 256 && tid + o < 256) add = shist[tid + o];
            __syncthreads();
            if (tid < 256) shist[tid] += add;
            __syncthreads();
        }
        if (tid < 256) {
            unsigned above = (tid < 255) ? shist[tid + 1] : 0u;
            if (shist[tid] >= kneed && above < kneed) {
                s_prefix = pref | ((unsigned)tid << shift);
                s_kneed  = kneed - above;
            }
        }
        __syncthreads();
    }
    unsigned thr = s_prefix;
    unsigned kprime = s_kneed;

    // tie-break: equals taken smallest-index-first, exactly kprime of them
    unsigned eq = 0;
    #pragma unroll
    for (int q = 0; q < 8; q++) eq += (uv[q] == thr);
    sscan[tid] = eq;
    __syncthreads();
    for (int o = 1; o < 1024; o <<= 1) {
        unsigned add = (tid >= o) ? sscan[tid - o] : 0u;
        __syncthreads();
        sscan[tid] += add;
        __syncthreads();
    }
    unsigned erank = sscan[tid] - eq;   // exclusive rank among equals
    int flags[8];
    #pragma unroll
    for (int q = 0; q < 8; q++) {
        unsigned u = uv[q];
        int f = 0;
        if (u > thr) f = 1;
        else if (u == thr) { f = (erank < kprime); erank++; }
        flags[q] = f;
        g_flags[base + q] = f;
    }
    __syncthreads();

    // build per-dst merge lists: counts -> offsets -> scatter
    #pragma unroll
    for (int q = 0; q < 8; q++) sarr[base + q] = 0u;
    __syncthreads();
    int dstk[8];
    #pragma unroll
    for (int q = 0; q < 8; q++) {
        if (flags[q]) {
            int i = base + q;
            int j = 1023 - dlow[q];
            dstk[q] = (i >> 10) * TB + j;
            atomicAdd(&sarr[dstk[q]], 1u);
        } else dstk[q] = -1;
    }
    __syncthreads();
    unsigned lc[8]; unsigned lsum = 0;
    #pragma unroll
    for (int q = 0; q < 8; q++) { lc[q] = sarr[base + q]; lsum += lc[q]; }
    sscan[tid] = lsum;
    __syncthreads();
    for (int o = 1; o < 1024; o <<= 1) {
        unsigned add = (tid >= o) ? sscan[tid - o] : 0u;
        __syncthreads();
        sscan[tid] += add;
        __syncthreads();
    }
    unsigned run = sscan[tid] - lsum;   // exclusive base for this thread's 8 dsts
    #pragma unroll
    for (int q = 0; q < 8; q++) {
        g_dstoff[base + q] = (int)run;
        g_dstdeg[base + q] = (int)lc[q];
        sarr[base + q] = run;           // cursor
        run += lc[q];
    }
    __syncthreads();
    #pragma unroll
    for (int q = 0; q < 8; q++) {
        if (dstk[q] >= 0) {
            unsigned pos = atomicAdd(&sarr[dstk[q]], 1u);
            g_dstlist[pos] = base + q;
        }
    }
}

// ---------------- per-batch output-order table ----------------
__global__ void k_plan() {
    __shared__ int s[1024];
    int b = blockIdx.x, tid = threadIdx.x;
    int f = g_flags[b*TA + tid];
    s[tid] = f;
    __syncthreads();
    #pragma unroll
    for (int o = 1; o < 1024; o <<= 1) {
        int v = (tid >= o) ? s[tid - o] : 0;
        __syncthreads();
        s[tid] += v;
        __syncthreads();
    }
    int mb = s[1023];           // merged count in this batch
    int rank_m = s[tid] - f;    // exclusive merged rank
    int* tab = g_table + b*T_FULL;
    if (f) tab[2048 - mb + rank_m] = -1;          // merged src -> tail slot
    else   tab[tid - rank_m]       = 2*tid;       // unmerged src, original order
    tab[(1024 - mb) + tid] = 2*tid + 1;           // dst rows
}

// ---------------- final gather/divide + size_s + pad_s ----------------
__global__ void __launch_bounds__(256) k_out(const float* __restrict__ x,
                                             const float* __restrict__ size,
                                             float* __restrict__ out) {
    int row = blockIdx.x;               // b*2048 + t
    int b = row >> 11;
    int tid = threadIdx.x;
    int code = g_table[row];
    float4* orow = reinterpret_cast<float4*>(out + (size_t)row*C_DIM);

    if (code < 0) {                     // merged tail slot: zeros, size 0, pad 1
        orow[tid] = make_float4(0.f,0.f,0.f,0.f);
        if (tid == 0) { out[X_ELEMS + row] = 0.f; out[X_ELEMS + BATCH*T_FULL + row] = 1.f; }
        return;
    }
    const float4* xrow = reinterpret_cast<const float4*>(x + ((size_t)(b*T_FULL + code))*C_DIM);
    float sv = size[b*T_FULL + code];
    float4 v = xrow[tid];
    float4 acc; acc.x = v.x*sv; acc.y = v.y*sv; acc.z = v.z*sv; acc.w = v.w*sv;
    float ssum = sv;
    if (code & 1) {                     // dst row: gather merged srcs
        int d = b*TB + (code >> 1);
        int off = g_dstoff[d], deg = g_dstdeg[d];
        for (int e = 0; e < deg; e++) {
            int si = g_dstlist[off + e];
            int srow = (si >> 10)*T_FULL + 2*(si & 1023);
            float ssv = size[srow];
            const float4* sx = reinterpret_cast<const float4*>(x + (size_t)srow*C_DIM);
            float4 a = sx[tid];
            acc.x += a.x*ssv; acc.y += a.y*ssv; acc.z += a.z*ssv; acc.w += a.w*ssv;
            ssum += ssv;
        }
    }
    float invd = 1.0f / (ssum + 1e-4f);
    float4 r; r.x = acc.x*invd; r.y = acc.y*invd; r.z = acc.z*invd; r.w = acc.w*invd;
    orow[tid] = r;
    if (tid == 0) { out[X_ELEMS + row] = ssum; out[X_ELEMS + BATCH*T_FULL + row] = 0.f; }
}

// ---------------- launch ----------------
extern "C" void kernel_launch(void* const* d_in, const int* in_sizes, int n_in,
                              void* d_out, int out_size) {
    const float* x      = (const float*)d_in[0];
    const float* metric = (const float*)d_in[1];
    const float* size   = (const float*)d_in[2];
    float* out = (float*)d_out;
    (void)in_sizes; (void)n_in; (void)out_size;

    dim3 g2(TB/JC, 4, BATCH);          // (16, 4, 8)
    k_scores<<<g2, 128>>>(metric);
    k_topk<<<1, 1024>>>();
    k_plan<<<BATCH, 1024>>>();
    k_out<<<BATCH*T_FULL, 256>>>(x, size, out);
}

// round 3
// speedup vs baseline: 1.3444x; 1.1030x over previous
#include <cuda_runtime.h>
#include <cstdint>

#define BATCH 8
#define T_FULL 2048
#define C_DIM 1024
#define H_DIM 64
#define TA 1024
#define TB 1024
#define R_MERGE 512
#define RB (R_MERGE*BATCH)   /* 4096 */
#define NROWS (BATCH*TA)     /* 8192 */
#define X_ELEMS (BATCH*T_FULL*C_DIM)  /* 16777216 */

// ---------------- scratch (__device__ globals; zero-initialized .bss) ----------------
__device__ unsigned long long g_pack[NROWS];     // per a-row: (flip(max)<<32)|(1023-argmax); reset by k_select
__device__ int g_table[BATCH*T_FULL];            // output row -> token code (2i even / 2j+1 odd / -1 tail)
__device__ int g_dstoff[NROWS];                  // per dst (b*TB+j): start offset into g_dstlist
__device__ int g_dstdeg[NROWS];                  // per dst: number of merged srcs
__device__ int g_dstlist[RB];                    // merged src a-row indices grouped by dst

// monotone float -> u32 map (order preserving)
__device__ __forceinline__ unsigned fflip(float f) {
    unsigned u = __float_as_uint(f);
    return (u & 0x80000000u) ? ~u : (u | 0x80000000u);
}

// ---------------- scores: per a-row max/argmax over all b via FFMA2 ----------------
#define JC 64
__global__ void __launch_bounds__(128, 2) k_scores(const float* __restrict__ metric) {
    __shared__ unsigned long long bsh[JC*H_DIM];   // 32 KB, (v,v) duplicated f32x2
    int jchunk = blockIdx.x;      // 0..15
    int atile  = blockIdx.y;      // 0..3
    int b      = blockIdx.z;      // 0..7
    int tid = threadIdx.x, lane = tid & 31, warp = tid >> 5;

    // load + normalize b rows (odd tokens) into smem, duplicated as f32x2
    for (int jj = warp; jj < JC; jj += 4) {
        const float* row = metric + ((size_t)(b*T_FULL + 2*(jchunk*JC + jj) + 1))*H_DIM;
        float v0 = row[lane], v1 = row[lane + 32];
        float ss = v0*v0 + v1*v1;
        #pragma unroll
        for (int o = 16; o; o >>= 1) ss += __shfl_xor_sync(0xffffffffu, ss, o);
        float inv = 1.0f / sqrtf(ss);
        float n0 = v0*inv, n1 = v1*inv;
        unsigned long long p0, p1;
        asm("mov.b64 %0, {%1,%1};" : "=l"(p0) : "r"(__float_as_uint(n0)));
        asm("mov.b64 %0, {%1,%1};" : "=l"(p1) : "r"(__float_as_uint(n1)));
        bsh[jj*H_DIM + lane]      = p0;
        bsh[jj*H_DIM + lane + 32] = p1;
    }

    // two a-rows per thread, RAW values packed (row0 lo, row1 hi); scale dot at the end
    int r0 = atile*256 + tid;
    int r1 = r0 + 128;
    const float4* a0 = (const float4*)(metric + ((size_t)(b*T_FULL + 2*r0))*H_DIM);
    const float4* a1 = (const float4*)(metric + ((size_t)(b*T_FULL + 2*r1))*H_DIM);
    unsigned long long ap[H_DIM];
    float ss0 = 0.f, ss1 = 0.f;
    #pragma unroll
    for (int k = 0; k < H_DIM/4; k++) {
        float4 f0 = a0[k], f1 = a1[k];
        ss0 += f0.x*f0.x + f0.y*f0.y + f0.z*f0.z + f0.w*f0.w;
        ss1 += f1.x*f1.x + f1.y*f1.y + f1.z*f1.z + f1.w*f1.w;
        asm("mov.b64 %0, {%1,%2};" : "=l"(ap[4*k+0]) : "f"(f0.x), "f"(f1.x));
        asm("mov.b64 %0, {%1,%2};" : "=l"(ap[4*k+1]) : "f"(f0.y), "f"(f1.y));
        asm("mov.b64 %0, {%1,%2};" : "=l"(ap[4*k+2]) : "f"(f0.z), "f"(f1.z));
        asm("mov.b64 %0, {%1,%2};" : "=l"(ap[4*k+3]) : "f"(f0.w), "f"(f1.w));
    }
    float i0 = 1.0f / sqrtf(ss0), i1 = 1.0f / sqrtf(ss1);
    __syncthreads();

    float m0 = -3e38f, m1 = -3e38f;
    int j0 = 0, j1 = 0;
    for (int j = 0; j < JC; j++) {
        const ulonglong2* bj = (const ulonglong2*)&bsh[j*H_DIM];
        unsigned long long ac0 = 0ULL, ac1 = 0ULL, ac2 = 0ULL, ac3 = 0ULL;
        #pragma unroll
        for (int k2 = 0; k2 < H_DIM/2; k2 += 2) {
            ulonglong2 q0 = bj[k2], q1 = bj[k2+1];
            asm("fma.rn.f32x2 %0, %1, %2, %0;" : "+l"(ac0) : "l"(ap[2*k2+0]), "l"(q0.x));
            asm("fma.rn.f32x2 %0, %1, %2, %0;" : "+l"(ac1) : "l"(ap[2*k2+1]), "l"(q0.y));
            asm("fma.rn.f32x2 %0, %1, %2, %0;" : "+l"(ac2) : "l"(ap[2*k2+2]), "l"(q1.x));
            asm("fma.rn.f32x2 %0, %1, %2, %0;" : "+l"(ac3) : "l"(ap[2*k2+3]), "l"(q1.y));
        }
        asm("add.rn.f32x2 %0, %0, %1;" : "+l"(ac0) : "l"(ac1));
        asm("add.rn.f32x2 %0, %0, %1;" : "+l"(ac2) : "l"(ac3));
        asm("add.rn.f32x2 %0, %0, %1;" : "+l"(ac0) : "l"(ac2));
        float d0 = __uint_as_float((unsigned)(ac0 & 0xffffffffu)) * i0;
        float d1 = __uint_as_float((unsigned)(ac0 >> 32)) * i1;
        int jg = jchunk*JC + j;
        if (d0 > m0) { m0 = d0; j0 = jg; }   // strict > keeps first max
        if (d1 > m1) { m1 = d1; j1 = jg; }
    }
    unsigned long long p0 = ((unsigned long long)fflip(m0) << 32) | (unsigned)(1023 - j0);
    unsigned long long p1 = ((unsigned long long)fflip(m1) << 32) | (unsigned)(1023 - j1);
    atomicMax(&g_pack[b*TA + r0], p0);
    atomicMax(&g_pack[b*TA + r1], p1);
}

// ---------------- block exclusive scan (sum), 1024 threads, shfl-based ----------------
__device__ __forceinline__ unsigned block_exscan(unsigned v, unsigned* swarp,
                                                 int lane, int wid) {
    __syncthreads();                          // protect swarp reuse across calls
    unsigned inc = v;
    #pragma unroll
    for (int o = 1; o < 32; o <<= 1) {
        unsigned t = __shfl_up_sync(0xffffffffu, inc, o);
        if (lane >= o) inc += t;
    }
    if (lane == 31) swarp[wid] = inc;
    __syncthreads();
    if (wid == 0) {
        unsigned w = swarp[lane];
        unsigned wi = w;
        #pragma unroll
        for (int o = 1; o < 32; o <<= 1) {
            unsigned t = __shfl_up_sync(0xffffffffu, wi, o);
            if (lane >= o) wi += t;
        }
        swarp[lane] = wi - w;                 // exclusive warp offsets
    }
    __syncthreads();
    return swarp[wid] + inc - v;
}

// ---------------- fused: top-RB radix select + flags + plan table + merge lists ----------------
__global__ void __launch_bounds__(1024) k_select() {
    __shared__ unsigned sarr[NROWS];          // 32KB: dst counts then cursor
    __shared__ unsigned shist[256];
    __shared__ unsigned swarp[32];
    __shared__ unsigned sbatch[9];
    __shared__ unsigned s_prefix, s_kneed;
    int tid = threadIdx.x, lane = tid & 31, wid = tid >> 5;
    int base = tid * 8;

    // load owned 8 rows; reset g_pack for next graph replay
    unsigned uv[8]; int dlow[8];
    #pragma unroll
    for (int q = 0; q < 8; q++) {
        unsigned long long p = g_pack[base + q];
        uv[q]   = (unsigned)(p >> 32);
        dlow[q] = (int)(p & 0xffffffffu);
        g_pack[base + q] = 0ULL;
    }
    if (tid == 0) { s_prefix = 0u; s_kneed = RB; }

    // ---- 4-pass radix select (exact threshold), warp0 suffix scans ----
    for (int byte = 3; byte >= 0; byte--) {
        int shift = byte * 8;
        unsigned maskhi = (byte == 3) ? 0u : (0xFFFFFFFFu << ((byte + 1) * 8));
        if (tid < 256) shist[tid] = 0u;
        __syncthreads();
        unsigned pref = s_prefix, kneed = s_kneed;
        #pragma unroll
        for (int q = 0; q < 8; q++) {
            unsigned u = uv[q];
            if ((u & maskhi) == pref) atomicAdd(&shist[(u >> shift) & 255u], 1u);
        }
        __syncthreads();
        if (wid == 0) {                       // suffix sums of 256 bins in one warp
            unsigned h[8]; unsigned c = 0;
            int b0 = lane * 8;
            #pragma unroll
            for (int j = 0; j < 8; j++) { h[j] = shist[b0 + j]; c += h[j]; }
            unsigned s = c;
            #pragma unroll
            for (int o = 1; o < 32; o <<= 1) {
                unsigned t = __shfl_down_sync(0xffffffffu, s, o);
                if (lane + o < 32) s += t;
            }
            unsigned run = s - c;             // chunks strictly above this lane
            #pragma unroll
            for (int j = 7; j >= 0; j--) { run += h[j]; shist[b0 + j] = run; }
        }
        __syncthreads();
        if (tid < 256) {
            unsigned S = shist[tid];
            unsigned above = (tid < 255) ? shist[tid + 1] : 0u;
            if (S >= kneed && above < kneed) {
                s_prefix = pref | ((unsigned)tid << shift);
                s_kneed  = kneed - above;
            }
        }
        __syncthreads();
    }
    unsigned thr = s_prefix;
    unsigned kprime = s_kneed;

    // ---- tie-break: equals taken smallest-index-first ----
    unsigned eq = 0;
    #pragma unroll
    for (int q = 0; q < 8; q++) eq += (uv[q] == thr);
    unsigned erank = block_exscan(eq, swarp, lane, wid);
    int flags[8]; unsigned fsum = 0;
    #pragma unroll
    for (int q = 0; q < 8; q++) {
        unsigned u = uv[q];
        int f = 0;
        if (u > thr) f = 1;
        else if (u == thr) { f = (erank < kprime); erank++; }
        flags[q] = f; fsum += f;
    }

    // ---- plan: per-batch stable ordering table ----
    unsigned fex = block_exscan(fsum, swarp, lane, wid);
    if ((tid & 127) == 0) sbatch[tid >> 7] = fex;
    if (tid == 1023)      sbatch[8] = fex + fsum;
    __syncthreads();
    {
        int b = tid >> 7;
        unsigned bb = sbatch[b];
        unsigned mb = sbatch[b + 1] - bb;
        unsigned run = fex - bb;              // merged rank before my rows, within batch
        int* tab = g_table + b * T_FULL;
        #pragma unroll
        for (int q = 0; q < 8; q++) {
            int il = (base + q) & 1023;
            if (flags[q]) { tab[2048 - (int)mb + (int)run] = -1; run++; }
            else            tab[il - (int)run] = 2 * il;
            tab[(1024 - (int)mb) + il] = 2 * il + 1;
        }
    }

    // ---- per-dst merge lists: counts -> offsets -> scatter ----
    __syncthreads();
    #pragma unroll
    for (int q = 0; q < 8; q++) sarr[base + q] = 0u;
    __syncthreads();
    int dstk[8];
    #pragma unroll
    for (int q = 0; q < 8; q++) {
        if (flags[q]) {
            int j = 1023 - dlow[q];
            dstk[q] = ((base + q) >> 10) * TB + j;
            atomicAdd(&sarr[dstk[q]], 1u);
        } else dstk[q] = -1;
    }
    __syncthreads();
    unsigned lc[8]; unsigned lsum = 0;
    #pragma unroll
    for (int q = 0; q < 8; q++) { lc[q] = sarr[base + q]; lsum += lc[q]; }
    unsigned run2 = block_exscan(lsum, swarp, lane, wid);
    #pragma unroll
    for (int q = 0; q < 8; q++) {
        g_dstoff[base + q] = (int)run2;
        g_dstdeg[base + q] = (int)lc[q];
        sarr[base + q] = run2;
        run2 += lc[q];
    }
    __syncthreads();
    #pragma unroll
    for (int q = 0; q < 8; q++) {
        if (dstk[q] >= 0) {
            unsigned pos = atomicAdd(&sarr[dstk[q]], 1u);
            g_dstlist[pos] = base + q;
        }
    }
}

// ---------------- final gather/divide + size_s + pad_s ----------------
__global__ void __launch_bounds__(256) k_out(const float* __restrict__ x,
                                             const float* __restrict__ size,
                                             float* __restrict__ out) {
    int row = blockIdx.x;               // b*2048 + t
    int b = row >> 11;
    int tid = threadIdx.x;
    int code = g_table[row];
    float4* orow = reinterpret_cast<float4*>(out + (size_t)row*C_DIM);

    if (code < 0) {                     // merged tail slot: zeros, size 0, pad 1
        __stcs(&orow[tid], make_float4(0.f,0.f,0.f,0.f));
        if (tid == 0) { out[X_ELEMS + row] = 0.f; out[X_ELEMS + BATCH*T_FULL + row] = 1.f; }
        return;
    }
    const float4* xrow = reinterpret_cast<const float4*>(x + ((size_t)(b*T_FULL + code))*C_DIM);
    float sv = size[b*T_FULL + code];
    float4 v = __ldcs(&xrow[tid]);
    float4 acc; acc.x = v.x*sv; acc.y = v.y*sv; acc.z = v.z*sv; acc.w = v.w*sv;
    float ssum = sv;
    if (code & 1) {                     // dst row: gather merged srcs
        int d = b*TB + (code >> 1);
        int off = g_dstoff[d], deg = g_dstdeg[d];
        for (int e = 0; e < deg; e++) {
            int si = g_dstlist[off + e];
            int srow = (si >> 10)*T_FULL + 2*(si & 1023);
            float ssv = size[srow];
            const float4* sx = reinterpret_cast<const float4*>(x + (size_t)srow*C_DIM);
            float4 a = __ldcs(&sx[tid]);
            acc.x += a.x*ssv; acc.y += a.y*ssv; acc.z += a.z*ssv; acc.w += a.w*ssv;
            ssum += ssv;
        }
    }
    float invd = 1.0f / (ssum + 1e-4f);
    float4 r; r.x = acc.x*invd; r.y = acc.y*invd; r.z = acc.z*invd; r.w = acc.w*invd;
    __stcs(&orow[tid], r);
    if (tid == 0) { out[X_ELEMS + row] = ssum; out[X_ELEMS + BATCH*T_FULL + row] = 0.f; }
}

// ---------------- launch ----------------
extern "C" void kernel_launch(void* const* d_in, const int* in_sizes, int n_in,
                              void* d_out, int out_size) {
    const float* x      = (const float*)d_in[0];
    const float* metric = (const float*)d_in[1];
    const float* size   = (const float*)d_in[2];
    float* out = (float*)d_out;
    (void)in_sizes; (void)n_in; (void)out_size;

    dim3 g2(TB/JC, 4, BATCH);          // (16, 4, 8)
    k_scores<<<g2, 128>>>(metric);
    k_select<<<1, 1024>>>();
    k_out<<<BATCH*T_FULL, 256>>>(x, size, out);
}

// round 5
// speedup vs baseline: 1.4372x; 1.0690x over previous
#include <cuda_runtime.h>
#include <cstdint>

#define BATCH 8
#define T_FULL 2048
#define C_DIM 1024
#define H_DIM 64
#define TA 1024
#define TB 1024
#define R_MERGE 512
#define RB (R_MERGE*BATCH)   /* 4096 */
#define NROWS (BATCH*TA)     /* 8192 */
#define X_ELEMS (BATCH*T_FULL*C_DIM)  /* 16777216 */

typedef unsigned long long u64;

// ---------------- scratch (__device__ globals; zero-initialized .bss) ----------------
__device__ u64 g_pack[NROWS];                  // (flip(max)<<32)|(1023-argmax); reset by k_select
__device__ int g_table[BATCH*T_FULL];
__device__ int g_dstoff[NROWS];
__device__ int g_dstdeg[NROWS];
__device__ int g_dstlist[RB];
// normalized-b, duplicated (v,v) f32x2, chunked: [b][chunk32][k32][j64]; chunk = jt*2+kc
__device__ __align__(16) u64 g_bd[BATCH*32*32*64];   // 4 MB
__device__ float g_ainv[NROWS];                // 1/||a_row||

__device__ __forceinline__ unsigned fflip(float f) {
    unsigned u = __float_as_uint(f);
    return (u & 0x80000000u) ? ~u : (u | 0x80000000u);
}
__device__ __forceinline__ u64 packf2(float lo, float hi) {
    u64 r; asm("mov.b64 %0, {%1,%2};" : "=l"(r) : "f"(lo), "f"(hi)); return r;
}
#define FMA2(acc, av, bv) asm("fma.rn.f32x2 %0, %1, %2, %0;" : "+l"(acc) : "l"(av), "l"(bv))

// ---------------- prep: normalize b tokens, write duplicated chunked layout ----------------
__global__ void __launch_bounds__(256) k_prep(const float* __restrict__ metric) {
    __shared__ float st[64][65];
    int jt = blockIdx.x;          // 0..15 (64-j tiles)
    int b  = blockIdx.y;
    int tid = threadIdx.x, lane = tid & 31, w = tid >> 5;

    // stage 64 b-token rows (odd tokens), coalesced
    for (int idx = tid; idx < 64*64; idx += 256) {
        int t = idx >> 6, k = idx & 63;
        st[t][k] = metric[((size_t)(b*T_FULL + 2*(jt*64 + t) + 1))*H_DIM + k];
    }
    __syncthreads();
    // normalize in place: warp w handles tokens w*8..w*8+7
    for (int t = w*8; t < w*8 + 8; t++) {
        float v0 = st[t][lane], v1 = st[t][lane+32];
        float ss = v0*v0 + v1*v1;
        #pragma unroll
        for (int o = 16; o; o >>= 1) ss += __shfl_xor_sync(0xffffffffu, ss, o);
        float inv = 1.0f / sqrtf(ss);
        st[t][lane] = v0*inv; st[t][lane+32] = v1*inv;
    }
    __syncthreads();
    // transpose-write duplicated: chunk = jt*2+kc, entry [k32][jl]
    for (int idx = tid; idx < 4096; idx += 256) {
        int kc = idx >> 11, k32 = (idx >> 6) & 31, jl = idx & 63;
        float v = st[jl][kc*32 + k32];
        g_bd[(((size_t)(b*32 + jt*2 + kc))*32 + k32)*64 + jl] = packf2(v, v);
    }
}

// ---------------- a-row inverse norms ----------------
__global__ void __launch_bounds__(256) k_anorm(const float* __restrict__ metric) {
    int w = threadIdx.x >> 5, lane = threadIdx.x & 31;
    int row = blockIdx.x*8 + w;                 // 0..8191
    int b = row >> 10;
    const float* m = metric + ((size_t)(b*T_FULL + 2*(row & 1023)))*H_DIM;
    float v0 = m[lane], v1 = m[lane+32];
    float ss = v0*v0 + v1*v1;
    #pragma unroll
    for (int o = 16; o; o >>= 1) ss += __shfl_xor_sync(0xffffffffu, ss, o);
    if (lane == 0) g_ainv[row] = 1.0f / sqrtf(ss);
}

// ---------------- scores: 16 rows/warp x 64 j, cp.async double-buffered ----------------
__global__ void __launch_bounds__(128) k_scores(const float* __restrict__ metric) {
    __shared__ __align__(16) unsigned char smem_raw[49152];
    u64* sa   = (u64*)smem_raw;                        // [64k][32rp] 16KB
    u64* sbuf = (u64*)(smem_raw + 16384);              // 2 x 16KB b chunks
    float (*staged)[65] = (float(*)[65])(smem_raw + 16384);  // overlaps sbuf (prologue only)

    int rowblk = blockIdx.x;     // 0..15 (64 rows)
    int jhalf  = blockIdx.y;     // 0..1
    int b      = blockIdx.z;     // 0..7
    int tid = threadIdx.x, l = tid & 31, w = tid >> 5;

    // stage raw a rows (even tokens), coalesced
    for (int idx = tid; idx < 64*64; idx += 128) {
        int rl = idx >> 6, k = idx & 63;
        staged[rl][k] = metric[((size_t)(b*T_FULL + 2*(rowblk*64 + rl)))*H_DIM + k];
    }
    __syncthreads();
    // build row-pair packed a: sa[k*32+rp] = (a[2rp][k], a[2rp+1][k])
    for (int idx = tid; idx < 2048; idx += 128) {
        int k = idx >> 5, rp = idx & 31;
        sa[k*32 + rp] = packf2(staged[2*rp][k], staged[2*rp+1][k]);
    }
    __syncthreads();

    // prefetch chunk 0
    const unsigned char* gsrc0 = (const unsigned char*)&g_bd[((size_t)(b*32 + jhalf*16))*2048];
    {
        unsigned sdst = (unsigned)__cvta_generic_to_shared(((unsigned char*)sbuf) + tid*16);
        #pragma unroll
        for (int i = 0; i < 8; i++)
            asm volatile("cp.async.cg.shared.global [%0], [%1], 16;"
                         :: "r"(sdst + i*2048), "l"(gsrc0 + tid*16 + i*2048));
        asm volatile("cp.async.commit_group;");
    }

    u64 acc[16];
    float rmax[16]; int rjdx[16];
    #pragma unroll
    for (int i = 0; i < 16; i++) { rmax[i] = -3.0e38f; rjdx[i] = 0; }

    for (int c = 0; c < 16; c++) {
        if (c + 1 < 16) {
            const unsigned char* gs = (const unsigned char*)&g_bd[((size_t)(b*32 + jhalf*16 + c + 1))*2048];
            unsigned sdst = (unsigned)__cvta_generic_to_shared(
                ((unsigned char*)sbuf) + (((c+1)&1)*16384) + tid*16);
            #pragma unroll
            for (int i = 0; i < 8; i++)
                asm volatile("cp.async.cg.shared.global [%0], [%1], 16;"
                             :: "r"(sdst + i*2048), "l"(gs + tid*16 + i*2048));
            asm volatile("cp.async.commit_group;");
            asm volatile("cp.async.wait_group 1;");
        } else {
            asm volatile("cp.async.wait_group 0;");
        }
        __syncthreads();

        int kc = c & 1;
        if (!kc) {
            #pragma unroll
            for (int i = 0; i < 16; i++) acc[i] = 0ULL;
        }
        const u64* bbase = sbuf + (c & 1)*2048 + 2*l;
        const u64* abase = sa + kc*32*32 + 8*w;
        #pragma unroll 4
        for (int k32 = 0; k32 < 32; k32++) {
            ulonglong2 bq = *(const ulonglong2*)(bbase + k32*64);
            const u64* ar = abase + k32*32;
            ulonglong2 a0 = *(const ulonglong2*)(ar);
            ulonglong2 a1 = *(const ulonglong2*)(ar + 2);
            ulonglong2 a2 = *(const ulonglong2*)(ar + 4);
            ulonglong2 a3 = *(const ulonglong2*)(ar + 6);
            FMA2(acc[ 0], a0.x, bq.x); FMA2(acc[ 1], a0.x, bq.y);
            FMA2(acc[ 2], a0.y, bq.x); FMA2(acc[ 3], a0.y, bq.y);
            FMA2(acc[ 4], a1.x, bq.x); FMA2(acc[ 5], a1.x, bq.y);
            FMA2(acc[ 6], a1.y, bq.x); FMA2(acc[ 7], a1.y, bq.y);
            FMA2(acc[ 8], a2.x, bq.x); FMA2(acc[ 9], a2.x, bq.y);
            FMA2(acc[10], a2.y, bq.x); FMA2(acc[11], a2.y, bq.y);
            FMA2(acc[12], a3.x, bq.x); FMA2(acc[13], a3.x, bq.y);
            FMA2(acc[14], a3.y, bq.x); FMA2(acc[15], a3.y, bq.y);
        }
        if (kc) {   // epilogue for this 64-j tile
            int jb = jhalf*512 + (c >> 1)*64 + 2*l;
            #pragma unroll
            for (int rp = 0; rp < 8; rp++) {
                #pragma unroll
                for (int jj = 0; jj < 2; jj++) {
                    u64 a = acc[rp*2 + jj];
                    float lo = __uint_as_float((unsigned)(a & 0xffffffffu));
                    float hi = __uint_as_float((unsigned)(a >> 32));
                    int j = jb + jj;
                    if (lo > rmax[2*rp])   { rmax[2*rp]   = lo; rjdx[2*rp]   = j; }
                    if (hi > rmax[2*rp+1]) { rmax[2*rp+1] = hi; rjdx[2*rp+1] = j; }
                }
            }
        }
        __syncthreads();
    }

    // final: scale by 1/||a||, cross-lane reduce, atomicMax
    int growbase = rowblk*64 + w*16;
    #pragma unroll
    for (int i = 0; i < 16; i++) {
        int grow = growbase + i;
        float inv = __ldg(&g_ainv[b*TA + grow]);
        u64 pk = ((u64)fflip(rmax[i]*inv) << 32) | (unsigned)(1023 - rjdx[i]);
        #pragma unroll
        for (int o = 16; o; o >>= 1) {
            u64 other = __shfl_down_sync(0xffffffffu, pk, o);
            if (other > pk) pk = other;
        }
        if (l == 0) atomicMax(&g_pack[b*TA + grow], pk);
    }
}

// ---------------- block exclusive scan (sum), 1024 threads ----------------
__device__ __forceinline__ unsigned block_exscan(unsigned v, unsigned* swarp,
                                                 int lane, int wid) {
    __syncthreads();
    unsigned inc = v;
    #pragma unroll
    for (int o = 1; o < 32; o <<= 1) {
        unsigned t = __shfl_up_sync(0xffffffffu, inc, o);
        if (lane >= o) inc += t;
    }
    if (lane == 31) swarp[wid] = inc;
    __syncthreads();
    if (wid == 0) {
        unsigned wv = swarp[lane];
        unsigned wi = wv;
        #pragma unroll
        for (int o = 1; o < 32; o <<= 1) {
            unsigned t = __shfl_up_sync(0xffffffffu, wi, o);
            if (lane >= o) wi += t;
        }
        swarp[lane] = wi - wv;
    }
    __syncthreads();
    return swarp[wid] + inc - v;
}

// ---------------- fused: top-RB radix select + plan + merge lists ----------------
__global__ void __launch_bounds__(1024) k_select() {
    __shared__ unsigned sarr[NROWS];
    __shared__ unsigned shist[256];
    __shared__ unsigned swarp[32];
    __shared__ unsigned sbatch[9];
    __shared__ unsigned s_prefix, s_kneed;
    int tid = threadIdx.x, lane = tid & 31, wid = tid >> 5;
    int base = tid * 8;

    unsigned uv[8]; int dlow[8];
    #pragma unroll
    for (int q = 0; q < 8; q++) {
        u64 p = g_pack[base + q];
        uv[q]   = (unsigned)(p >> 32);
        dlow[q] = (int)(p & 0xffffffffu);
        g_pack[base + q] = 0ULL;        // reset for next replay (atomicMax combine)
    }
    if (tid == 0) { s_prefix = 0u; s_kneed = RB; }

    for (int byte = 3; byte >= 0; byte--) {
        int shift = byte * 8;
        unsigned maskhi = (byte == 3) ? 0u : (0xFFFFFFFFu << ((byte + 1) * 8));
        if (tid < 256) shist[tid] = 0u;
        __syncthreads();
        unsigned pref = s_prefix, kneed = s_kneed;
        #pragma unroll
        for (int q = 0; q < 8; q++) {
            unsigned u = uv[q];
            if ((u & maskhi) == pref) atomicAdd(&shist[(u >> shift) & 255u], 1u);
        }
        __syncthreads();
        if (wid == 0) {
            unsigned h[8]; unsigned cc = 0;
            int b0 = lane * 8;
            #pragma unroll
            for (int j = 0; j < 8; j++) { h[j] = shist[b0 + j]; cc += h[j]; }
            unsigned s = cc;
            #pragma unroll
            for (int o = 1; o < 32; o <<= 1) {
                unsigned t = __shfl_down_sync(0xffffffffu, s, o);
                if (lane + o < 32) s += t;
            }
            unsigned run = s - cc;
            #pragma unroll
            for (int j = 7; j >= 0; j--) { run += h[j]; shist[b0 + j] = run; }
        }
        __syncthreads();
        if (tid < 256) {
            unsigned S = shist[tid];
            unsigned above = (tid < 255) ? shist[tid + 1] : 0u;
            if (S >= kneed && above < kneed) {
                s_prefix = pref | ((unsigned)tid << shift);
                s_kneed  = kneed - above;
            }
        }
        __syncthreads();
    }
    unsigned thr = s_prefix;
    unsigned kprime = s_kneed;

    unsigned eq = 0;
    #pragma unroll
    for (int q = 0; q < 8; q++) eq += (uv[q] == thr);
    unsigned erank = block_exscan(eq, swarp, lane, wid);
    int flags[8]; unsigned fsum = 0;
    #pragma unroll
    for (int q = 0; q < 8; q++) {
        unsigned u = uv[q];
        int f = 0;
        if (u > thr) f = 1;
        else if (u == thr) { f = (erank < kprime); erank++; }
        flags[q] = f; fsum += f;
    }

    unsigned fex = block_exscan(fsum, swarp, lane, wid);
    if ((tid & 127) == 0) sbatch[tid >> 7] = fex;
    if (tid == 1023)      sbatch[8] = fex + fsum;
    __syncthreads();
    {
        int b = tid >> 7;
        unsigned bb = sbatch[b];
        unsigned mb = sbatch[b + 1] - bb;
        unsigned run = fex - bb;
        int* tab = g_table + b * T_FULL;
        #pragma unroll
        for (int q = 0; q < 8; q++) {
            int il = (base + q) & 1023;
            if (flags[q]) { tab[2048 - (int)mb + (int)run] = -1; run++; }
            else            tab[il - (int)run] = 2 * il;
            tab[(1024 - (int)mb) + il] = 2 * il + 1;
        }
    }

    __syncthreads();
    #pragma unroll
    for (int q = 0; q < 8; q++) sarr[base + q] = 0u;
    __syncthreads();
    int dstk[8];
    #pragma unroll
    for (int q = 0; q < 8; q++) {
        if (flags[q]) {
            int j = 1023 - dlow[q];
            dstk[q] = ((base + q) >> 10) * TB + j;
            atomicAdd(&sarr[dstk[q]], 1u);
        } else dstk[q] = -1;
    }
    __syncthreads();
    unsigned lc[8]; unsigned lsum = 0;
    #pragma unroll
    for (int q = 0; q < 8; q++) { lc[q] = sarr[base + q]; lsum += lc[q]; }
    unsigned run2 = block_exscan(lsum, swarp, lane, wid);
    #pragma unroll
    for (int q = 0; q < 8; q++) {
        g_dstoff[base + q] = (int)run2;
        g_dstdeg[base + q] = (int)lc[q];
        sarr[base + q] = run2;
        run2 += lc[q];
    }
    __syncthreads();
    #pragma unroll
    for (int q = 0; q < 8; q++) {
        if (dstk[q] >= 0) {
            unsigned pos = atomicAdd(&sarr[dstk[q]], 1u);
            g_dstlist[pos] = base + q;
        }
    }
}

// ---------------- final gather/divide + size_s + pad_s ----------------
__global__ void __launch_bounds__(256) k_out(const float* __restrict__ x,
                                             const float* __restrict__ size,
                                             float* __restrict__ out) {
    int row = blockIdx.x;
    int b = row >> 11;
    int tid = threadIdx.x;
    int code = g_table[row];
    float4* orow = reinterpret_cast<float4*>(out + (size_t)row*C_DIM);

    if (code < 0) {
        __stcs(&orow[tid], make_float4(0.f,0.f,0.f,0.f));
        if (tid == 0) { out[X_ELEMS + row] = 0.f; out[X_ELEMS + BATCH*T_FULL + row] = 1.f; }
        return;
    }
    const float4* xrow = reinterpret_cast<const float4*>(x + ((size_t)(b*T_FULL + code))*C_DIM);
    float sv = size[b*T_FULL + code];
    float4 v = __ldcs(&xrow[tid]);
    float4 acc; acc.x = v.x*sv; acc.y = v.y*sv; acc.z = v.z*sv; acc.w = v.w*sv;
    float ssum = sv;
    if (code & 1) {
        int d = b*TB + (code >> 1);
        int off = g_dstoff[d], deg = g_dstdeg[d];
        for (int e = 0; e < deg; e++) {
            int si = g_dstlist[off + e];
            int srow = (si >> 10)*T_FULL + 2*(si & 1023);
            float ssv = size[srow];
            const float4* sx = reinterpret_cast<const float4*>(x + (size_t)srow*C_DIM);
            float4 a = __ldcs(&sx[tid]);
            acc.x += a.x*ssv; acc.y += a.y*ssv; acc.z += a.z*ssv; acc.w += a.w*ssv;
            ssum += ssv;
        }
    }
    float invd = 1.0f / (ssum + 1e-4f);
    float4 r; r.x = acc.x*invd; r.y = acc.y*invd; r.z = acc.z*invd; r.w = acc.w*invd;
    __stcs(&orow[tid], r);
    if (tid == 0) { out[X_ELEMS + row] = ssum; out[X_ELEMS + BATCH*T_FULL + row] = 0.f; }
}

// ---------------- launch ----------------
extern "C" void kernel_launch(void* const* d_in, const int* in_sizes, int n_in,
                              void* d_out, int out_size) {
    const float* x      = (const float*)d_in[0];
    const float* metric = (const float*)d_in[1];
    const float* size   = (const float*)d_in[2];
    float* out = (float*)d_out;
    (void)in_sizes; (void)n_in; (void)out_size;

    k_prep<<<dim3(16, 8), 256>>>(metric);
    k_anorm<<<1024, 256>>>(metric);
    k_scores<<<dim3(16, 2, 8), 128>>>(metric);
    k_select<<<1, 1024>>>();
    k_out<<<BATCH*T_FULL, 256>>>(x, size, out);
}